// round 5
// baseline (speedup 1.0000x reference)
#include <cuda_runtime.h>
#include <cstdint>
#include <cstddef>

#define NB      64
#define NPRED   100800
#define KDET    512
#define CAP     8192
#define SEL     1024
#define CONF_T  0.7f
#define IOU_T   0.45f

#define K1_THREADS 256
#define K1_RPT     8                       // rows per thread
#define K1_ROWS    (K1_THREADS * K1_RPT)   // 2048
#define K1_BLKS    50                      // 50*2048 >= 100800

// Global scratch (__device__ arrays; no allocation).
__device__ float    g_sc[NB][CAP];
__device__ int      g_ix[NB][CAP];
__device__ int      g_cnt[NB];            // zero at load; reset by select_sort
__device__ float4   g_boxes[NB][KDET];
__device__ float    g_area[NB][KDET];
__device__ float    g_ssc[NB][KDET];
__device__ int      g_six[NB][KDET];
__device__ unsigned g_kw[NB][16];
__device__ unsigned g_mask[NB][KDET * 16];  // 2 MB

// ---------------------------------------------------------------------------
// Kernel 1: streaming-LDG scoring + two-level compaction. DRAM-bound.
// ---------------------------------------------------------------------------
__global__ __launch_bounds__(K1_THREADS)
void score_compact_kernel(const float* __restrict__ pred) {
    __shared__ float stg_sc[256];
    __shared__ int   stg_ix[256];
    __shared__ int   sCnt, blockBase;

    const int b   = blockIdx.y;
    const int tid = threadIdx.x;
    const int r0  = blockIdx.x * K1_ROWS;
    if (tid == 0) sCnt = 0;
    __syncthreads();

    const float* __restrict__ base = pred + (size_t)b * NPRED * 9;

    float a[K1_RPT], c[K1_RPT];
    #pragma unroll
    for (int k = 0; k < K1_RPT; k++) {          // front-batched loads (MLP 16)
        int r = r0 + k * K1_THREADS + tid;      // coalesced within each k
        const float* p = base + (size_t)r * 9;
        bool ok = r < NPRED;
        a[k] = ok ? __ldcs(p + 4) : 0.0f;       // evict-first: stream-once data
        c[k] = ok ? __ldcs(p + 5) : 0.0f;
    }
    #pragma unroll
    for (int k = 0; k < K1_RPT; k++) {
        float conf = __fmul_rn(a[k], c[k]);     // exact, matches reference
        if (conf > CONF_T) {
            int p = atomicAdd(&sCnt, 1);        // ~100 per block
            if (p < 256) { stg_sc[p] = conf; stg_ix[p] = r0 + k * K1_THREADS + tid; }
        }
    }
    __syncthreads();
    if (tid == 0) blockBase = atomicAdd(&g_cnt[b], sCnt);   // ONE global atomic
    __syncthreads();

    int n = min(sCnt, 256);
    int gbase = blockBase;
    for (int t = tid; t < n; t += K1_THREADS) {
        int p = gbase + t;
        if (p < CAP) { g_sc[b][p] = stg_sc[t]; g_ix[b][p] = stg_ix[t]; }
    }
}

// ---------------------------------------------------------------------------
// Kernel 2a: radix-select (hierarchical shfl suffix-scan) + hybrid bitonic(1024).
// ---------------------------------------------------------------------------
__global__ __launch_bounds__(1024, 1)
void select_sort_kernel(const float* __restrict__ pred) {
    __shared__ float bufS[2][SEL];     // 8 KB (double-buffer)
    __shared__ int   bufI[2][SEL];     // 8 KB
    __shared__ int   hist[1024];       // 4 KB
    __shared__ int   warpOff[32];
    __shared__ int   selCnt, b1s;

    const int tid  = threadIdx.x;
    const int lane = tid & 31;
    const int wrp  = tid >> 5;
    const int b    = blockIdx.x;
    int cnt = g_cnt[b];
    if (cnt > CAP) cnt = CAP;

    // Phase 1: histogram on score bits [22:13] (exponent fixed for (0.7,1))
    hist[tid] = 0;
    if (tid == 0) { selCnt = 0; b1s = -1; }
    __syncthreads();
    for (int e = tid; e < cnt; e += 1024) {
        unsigned u = __float_as_uint(g_sc[b][e]);
        atomicAdd(&hist[(u >> 13) & 1023], 1);
    }
    __syncthreads();

    // Phase 2: hierarchical inclusive SUFFIX scan of hist (3 barriers total)
    int val = hist[tid];
    #pragma unroll
    for (int d = 1; d < 32; d <<= 1) {
        int v = __shfl_down_sync(0xffffffffu, val, d);
        if (lane + d < 32) val += v;
    }
    // lane 0 now holds this warp's total
    if (lane == 0) warpOff[wrp] = val;
    __syncthreads();
    if (wrp == 0) {
        int t = warpOff[lane];
        int tot = t;
        #pragma unroll
        for (int d = 1; d < 32; d <<= 1) {
            int v = __shfl_down_sync(0xffffffffu, tot, d);
            if (lane + d < 32) tot += v;
        }
        warpOff[lane] = tot - t;            // exclusive suffix of warp totals
    }
    __syncthreads();
    int suffix = val + warpOff[wrp];        // sum of hist[u] for u >= tid
    int target = (cnt < KDET) ? cnt : KDET;
    if (suffix >= target) atomicMax(&b1s, tid);
    __syncthreads();
    int b1 = b1s;

    // Phase 3: collect bins >= b1 (~ target + boundary spill)
    for (int e = tid; e < cnt; e += 1024) {
        float sc = g_sc[b][e];
        if ((int)((__float_as_uint(sc) >> 13) & 1023) >= b1) {
            int p = atomicAdd(&selCnt, 1);
            if (p < SEL) { bufS[0][p] = sc; bufI[0][p] = g_ix[b][e]; }
        }
    }
    __syncthreads();
    int selN = selCnt; if (selN > SEL) selN = SEL;
    if (tid >= selN) { bufS[0][tid] = -1.0f; bufI[0][tid] = 0x7fffffff; }
    __syncthreads();

    // Phase 4: hybrid bitonic sort (score desc, idx asc == lax.top_k order)
    float s  = bufS[0][tid];
    int   ix = bufI[0][tid];
    int   pb = 1;
    for (int k = 2; k <= SEL; k <<= 1) {
        for (int j = k >> 1; j > 0; j >>= 1) {
            float s2; int i2;
            if (j >= 32) {
                bufS[pb][tid] = s; bufI[pb][tid] = ix;
                __syncthreads();
                s2 = bufS[pb][tid ^ j]; i2 = bufI[pb][tid ^ j];
                pb ^= 1;
            } else {
                s2 = __shfl_xor_sync(0xffffffffu, s, j);
                i2 = __shfl_xor_sync(0xffffffffu, ix, j);
            }
            bool want_first = ((tid & k) == 0);
            bool i_low      = ((tid & j) == 0);
            bool mine_better = (s > s2) || (s == s2 && ix < i2);
            if (mine_better != (i_low == want_first)) { s = s2; ix = i2; }
        }
    }

    // Phase 5: gather top-512 rows -> boxes/areas/validity, store to global.
    if (tid < KDET) {
        float4 bx = make_float4(0.f, 0.f, 0.f, 0.f);
        float  ar = 0.f;
        bool valid = s > CONF_T;
        if (valid) {
            const float* r = pred + ((size_t)b * NPRED + ix) * 9;
            float cx = r[0], cy = r[1];
            float hw = __fmul_rn(r[2], 0.5f);     // exact; matches ref rounding
            float hh = __fmul_rn(r[3], 0.5f);
            bx.x = __fsub_rn(cx, hw); bx.y = __fsub_rn(cy, hh);
            bx.z = __fadd_rn(cx, hw); bx.w = __fadd_rn(cy, hh);
            ar = __fmul_rn(__fsub_rn(bx.z, bx.x), __fsub_rn(bx.w, bx.y));
        }
        g_boxes[b][tid] = bx;
        g_area[b][tid]  = ar;
        g_ssc[b][tid]   = s;
        g_six[b][tid]   = ix;
        unsigned bal = __ballot_sync(0xffffffffu, valid);
        if (lane == 0) g_kw[b][tid >> 5] = ~bal;  // removed-init = !valid
    }
    if (tid == 0) g_cnt[b] = 0;   // reset for next graph replay
}

// ---------------------------------------------------------------------------
// Kernel 2b: full-chip IoU suppression bitmask. One warp-task = (row i, word w).
// ---------------------------------------------------------------------------
__global__ __launch_bounds__(256)
void mask_kernel() {
    __shared__ float4 Sb[KDET];    // 8 KB
    __shared__ float  Sa[KDET];    // 2 KB
    const int tid  = threadIdx.x;
    const int lane = tid & 31;
    const int wid  = tid >> 5;
    const int b    = blockIdx.y;

    for (int q = tid; q < KDET; q += 256) { Sb[q] = g_boxes[b][q]; Sa[q] = g_area[b][q]; }
    __syncthreads();

    int wg = blockIdx.x * 8 + wid;             // 0..127 within batch
    for (int T = wg; T < KDET * 16; T += 128) {
        int i = T >> 4;
        int w = T & 15;
        unsigned bits = 0;
        if ((w << 5) + 31 > i) {               // word contains some j > i
            float4 bi = Sb[i];                 // LDS broadcast
            float  ai = Sa[i];
            int    j  = (w << 5) + lane;
            float4 bj = Sb[j];
            float  aj = Sa[j];
            float xx1 = fmaxf(bi.x, bj.x), yy1 = fmaxf(bi.y, bj.y);
            float xx2 = fminf(bi.z, bj.z), yy2 = fminf(bi.w, bj.w);
            float iw = fmaxf(__fsub_rn(xx2, xx1), 0.f);
            float ih = fmaxf(__fsub_rn(yy2, yy1), 0.f);
            float inter = __fmul_rn(iw, ih);
            float denom = __fadd_rn(__fsub_rn(__fadd_rn(ai, aj), inter), 1e-7f);
            float t45 = __fmul_rn(denom, IOU_T);
            bool over;
            if      (inter > __fmul_rn(t45, 1.0000005f)) over = true;
            else if (inter < __fmul_rn(t45, 0.9999995f)) over = false;
            else    over = (__fdiv_rn(inter, denom) > IOU_T);   // exact fallback
            bits = __ballot_sync(0xffffffffu, over && (j > i));
        }
        if (lane == 0) g_mask[b][T] = bits;
    }
}

// ---------------------------------------------------------------------------
// Kernel 2c: warp-cooperative greedy suppression + latency-hidden output.
// ---------------------------------------------------------------------------
__global__ __launch_bounds__(512)
void greedy_out_kernel(const float* __restrict__ pred, float* __restrict__ out) {
    __shared__ unsigned Sm[KDET * 16];   // 32 KB
    __shared__ unsigned Skw[16];
    const int tid  = threadIdx.x;
    const int lane = tid & 31;
    const int b    = blockIdx.x;

    {   // stage mask into smem, coalesced uint4
        const uint4* src = (const uint4*)g_mask[b];
        uint4* dst = (uint4*)Sm;
        #pragma unroll
        for (int u = 0; u < 4; u++) dst[tid + 512 * u] = src[tid + 512 * u];
    }
    if (tid < 16) Skw[tid] = g_kw[b][tid];

    // Prefetch output payload NOW (indices known pre-greedy) to hide gather
    // latency behind the serial greedy scan.
    float4 bx = g_boxes[b][tid];
    float  sc = g_ssc[b][tid];
    int    ix = g_six[b][tid];
    const float* rr = pred + ((size_t)b * NPRED + ix) * 9;
    float p6 = __ldg(rr + 6), p7 = __ldg(rr + 7), p8 = __ldg(rr + 8);
    __syncthreads();

    // Warp 0: greedy scan. Lane l (mirrored at l+16) owns removed-word l&15.
    if (tid < 32) {
        const int l16 = lane & 15;
        unsigned rem = Skw[l16];
        const unsigned* rowp = Sm + l16;       // this lane's mask column
        #pragma unroll 1
        for (int wb = 0; wb < 16; wb++) {
            unsigned cur = __shfl_sync(0xffffffffu, rem, wb);  // word wb tracker
            const unsigned* curp = Sm + wb;
            const int ib = wb << 5;
            unsigned prA = rowp[(ib + 0) << 4];
            unsigned pcA = curp[(ib + 0) << 4];
            unsigned prB = rowp[(ib + 1) << 4];
            unsigned pcB = curp[(ib + 1) << 4];
            #pragma unroll
            for (int bit = 0; bit < 32; bit++) {
                unsigned row = prA, cw = pcA;
                prA = prB; pcA = pcB;
                int nx = bit + 2; if (nx > 31) nx = 31;
                prB = rowp[(ib + nx) << 4];
                pcB = curp[(ib + nx) << 4];
                if (!((cur >> bit) & 1u)) {    // box ib+bit survives -> suppress
                    rem |= row;
                    cur |= cw;
                }
            }
        }
        if (lane < 16) Skw[lane] = rem;
    }
    __syncthreads();

    // Output [b, KDET, 9] from registers
    bool kept = !((Skw[tid >> 5] >> (tid & 31)) & 1u);
    float* orow = out + ((size_t)b * KDET + tid) * 9;
    if (kept) {
        orow[0] = bx.x; orow[1] = bx.y; orow[2] = bx.z; orow[3] = bx.w;
        orow[4] = sc;
        orow[5] = 0.0f;
        orow[6] = p6; orow[7] = p7; orow[8] = p8;
    } else {
        #pragma unroll
        for (int q = 0; q < 9; q++) orow[q] = 0.0f;
    }
}

// ---------------------------------------------------------------------------
extern "C" void kernel_launch(void* const* d_in, const int* in_sizes, int n_in,
                              void* d_out, int out_size) {
    const float* pred = (const float*)d_in[0];
    float* out = (float*)d_out;

    score_compact_kernel<<<dim3(K1_BLKS, NB), K1_THREADS>>>(pred);
    select_sort_kernel<<<NB, 1024>>>(pred);
    mask_kernel<<<dim3(16, NB), 256>>>();
    greedy_out_kernel<<<NB, KDET>>>(pred, out);
}

// round 6
// speedup vs baseline: 1.2034x; 1.2034x over previous
#include <cuda_runtime.h>
#include <cstdint>
#include <cstddef>

#define NB      64
#define NPRED   100800
#define KDET    512
#define CAP     8192
#define SEL     1024
#define CONF_T  0.7f
#define IOU_T   0.45f

#define K1_THREADS 256
#define K1_RPT     8                       // rows per thread
#define K1_ROWS    (K1_THREADS * K1_RPT)   // 2048
#define K1_BLKS    50                      // 50*2048 >= 100800

#define MASK_BLKS_PER_B 16                 // blocks per batch in mask kernel

// Global scratch (__device__ arrays; no allocation).
__device__ float    g_sc[NB][CAP];
__device__ int      g_ix[NB][CAP];
__device__ int      g_cnt[NB];            // zero at load; reset by select_sort
__device__ float4   g_boxes[NB][KDET];
__device__ float    g_area[NB][KDET];
__device__ float    g_ssc[NB][KDET];
__device__ int      g_six[NB][KDET];
__device__ unsigned g_kw[NB][16];
__device__ unsigned g_mask[NB][KDET * 16];  // 2 MB
__device__ int      g_done[NB];             // zero at load; self-resetting

// ---------------------------------------------------------------------------
// Kernel 1: direct-LDG scoring + two-level compaction. DRAM-bound streamer.
// (identical to round-4 version: __ldg, front-batched MLP-16)
// ---------------------------------------------------------------------------
__global__ __launch_bounds__(K1_THREADS)
void score_compact_kernel(const float* __restrict__ pred) {
    __shared__ float stg_sc[256];
    __shared__ int   stg_ix[256];
    __shared__ int   sCnt, blockBase;

    const int b   = blockIdx.y;
    const int tid = threadIdx.x;
    const int r0  = blockIdx.x * K1_ROWS;
    if (tid == 0) sCnt = 0;
    __syncthreads();

    const float* __restrict__ base = pred + (size_t)b * NPRED * 9;

    float a[K1_RPT], c[K1_RPT];
    int   rr[K1_RPT];
    #pragma unroll
    for (int k = 0; k < K1_RPT; k++) {          // front-batched loads (MLP 16)
        int r = r0 + k * K1_THREADS + tid;      // coalesced within each k
        rr[k] = r;
        bool ok = r < NPRED;
        const float* p = base + (size_t)r * 9;
        a[k] = ok ? __ldg(p + 4) : 0.0f;
        c[k] = ok ? __ldg(p + 5) : 0.0f;
    }
    #pragma unroll
    for (int k = 0; k < K1_RPT; k++) {
        float conf = __fmul_rn(a[k], c[k]);     // exact, matches reference
        if (conf > CONF_T) {
            int p = atomicAdd(&sCnt, 1);        // ~100 per block
            if (p < 256) { stg_sc[p] = conf; stg_ix[p] = rr[k]; }
        }
    }
    __syncthreads();
    if (tid == 0) blockBase = atomicAdd(&g_cnt[b], sCnt);   // ONE global atomic
    __syncthreads();

    int n = min(sCnt, 256);
    int gbase = blockBase;
    for (int t = tid; t < n; t += K1_THREADS) {
        int p = gbase + t;
        if (p < CAP) { g_sc[b][p] = stg_sc[t]; g_ix[b][p] = stg_ix[t]; }
    }
}

// ---------------------------------------------------------------------------
// Kernel 2a: radix-select + hybrid register/shfl/smem bitonic(1024) + gather.
// (identical to round-4 version)
// ---------------------------------------------------------------------------
__global__ __launch_bounds__(1024, 1)
void select_sort_kernel(const float* __restrict__ pred) {
    __shared__ float bufS[2][SEL];     // 8 KB (double-buffer)
    __shared__ int   bufI[2][SEL];     // 8 KB
    __shared__ int   hist[1024];       // 4 KB
    __shared__ int   selCnt, b1s;

    const int tid = threadIdx.x;
    const int b   = blockIdx.x;
    int cnt = g_cnt[b];
    if (cnt > CAP) cnt = CAP;

    // Phase 1: histogram on score bits [22:13] (exponent fixed for (0.7,1))
    hist[tid] = 0;
    if (tid == 0) { selCnt = 0; b1s = -1; }
    __syncthreads();
    for (int e = tid; e < cnt; e += 1024) {
        unsigned u = __float_as_uint(g_sc[b][e]);
        atomicAdd(&hist[(u >> 13) & 1023], 1);
    }
    __syncthreads();

    // Phase 2: suffix sum + boundary bin
    for (int d = 1; d < 1024; d <<= 1) {
        int v = (tid + d < 1024) ? hist[tid + d] : 0;
        __syncthreads();
        hist[tid] += v;
        __syncthreads();
    }
    int target = (cnt < KDET) ? cnt : KDET;
    if (hist[tid] >= target) atomicMax(&b1s, tid);
    __syncthreads();
    int b1 = b1s;

    // Phase 3: collect bins >= b1 (~ target + boundary spill)
    for (int e = tid; e < cnt; e += 1024) {
        float sc = g_sc[b][e];
        if ((int)((__float_as_uint(sc) >> 13) & 1023) >= b1) {
            int p = atomicAdd(&selCnt, 1);
            if (p < SEL) { bufS[0][p] = sc; bufI[0][p] = g_ix[b][e]; }
        }
    }
    __syncthreads();
    int selN = selCnt; if (selN > SEL) selN = SEL;
    if (tid >= selN) { bufS[0][tid] = -1.0f; bufI[0][tid] = 0x7fffffff; }
    __syncthreads();

    // Phase 4: hybrid bitonic sort (score desc, idx asc == lax.top_k order)
    float s  = bufS[0][tid];
    int   ix = bufI[0][tid];
    int   pb = 1;
    for (int k = 2; k <= SEL; k <<= 1) {
        for (int j = k >> 1; j > 0; j >>= 1) {
            float s2; int i2;
            if (j >= 32) {
                bufS[pb][tid] = s; bufI[pb][tid] = ix;
                __syncthreads();
                s2 = bufS[pb][tid ^ j]; i2 = bufI[pb][tid ^ j];
                pb ^= 1;
            } else {
                s2 = __shfl_xor_sync(0xffffffffu, s, j);
                i2 = __shfl_xor_sync(0xffffffffu, ix, j);
            }
            bool want_first = ((tid & k) == 0);
            bool i_low      = ((tid & j) == 0);
            bool mine_better = (s > s2) || (s == s2 && ix < i2);
            if (mine_better != (i_low == want_first)) { s = s2; ix = i2; }
        }
    }

    // Phase 5: gather top-512 rows -> boxes/areas/validity, store to global.
    if (tid < KDET) {
        float4 bx = make_float4(0.f, 0.f, 0.f, 0.f);
        float  ar = 0.f;
        bool valid = s > CONF_T;
        if (valid) {
            const float* r = pred + ((size_t)b * NPRED + ix) * 9;
            float cx = r[0], cy = r[1];
            float hw = __fmul_rn(r[2], 0.5f);     // exact; matches ref rounding
            float hh = __fmul_rn(r[3], 0.5f);
            bx.x = __fsub_rn(cx, hw); bx.y = __fsub_rn(cy, hh);
            bx.z = __fadd_rn(cx, hw); bx.w = __fadd_rn(cy, hh);
            ar = __fmul_rn(__fsub_rn(bx.z, bx.x), __fsub_rn(bx.w, bx.y));
        }
        g_boxes[b][tid] = bx;
        g_area[b][tid]  = ar;
        g_ssc[b][tid]   = s;
        g_six[b][tid]   = ix;
        unsigned bal = __ballot_sync(0xffffffffu, valid);
        if ((tid & 31) == 0) g_kw[b][tid >> 5] = ~bal;  // removed-init = !valid
    }
    if (tid == 0) g_cnt[b] = 0;   // reset for next graph replay
}

// ---------------------------------------------------------------------------
// Kernel 2b: full-chip IoU mask + last-block greedy NMS + output (fused).
// grid (16, NB) x 256. The 16th finisher per batch runs greedy on L2-hot mask.
// ---------------------------------------------------------------------------
__global__ __launch_bounds__(256)
void mask_greedy_kernel(const float* __restrict__ pred, float* __restrict__ out) {
    __shared__ union {
        struct { float4 Sb[KDET]; float Sa[KDET]; } m;   // 10 KB (mask phase)
        unsigned Sm[KDET * 16];                          // 32 KB (greedy phase)
    } U;
    __shared__ unsigned Skw[16];
    __shared__ int isLast;

    const int tid  = threadIdx.x;
    const int lane = tid & 31;
    const int wid  = tid >> 5;
    const int b    = blockIdx.y;

    // ---- mask phase ----
    for (int q = tid; q < KDET; q += 256) {
        U.m.Sb[q] = g_boxes[b][q];
        U.m.Sa[q] = g_area[b][q];
    }
    __syncthreads();

    int wg = blockIdx.x * 8 + wid;             // 0..127 within batch
    for (int T = wg; T < KDET * 16; T += 128) {
        int i = T >> 4;
        int w = T & 15;
        unsigned bits = 0;
        if ((w << 5) + 31 > i) {               // word contains some j > i
            float4 bi = U.m.Sb[i];             // LDS broadcast
            float  ai = U.m.Sa[i];
            int    j  = (w << 5) + lane;
            float4 bj = U.m.Sb[j];
            float  aj = U.m.Sa[j];
            float xx1 = fmaxf(bi.x, bj.x), yy1 = fmaxf(bi.y, bj.y);
            float xx2 = fminf(bi.z, bj.z), yy2 = fminf(bi.w, bj.w);
            float iw = fmaxf(__fsub_rn(xx2, xx1), 0.f);
            float ih = fmaxf(__fsub_rn(yy2, yy1), 0.f);
            float inter = __fmul_rn(iw, ih);
            float denom = __fadd_rn(__fsub_rn(__fadd_rn(ai, aj), inter), 1e-7f);
            float t45 = __fmul_rn(denom, IOU_T);
            bool over;
            if      (inter > __fmul_rn(t45, 1.0000005f)) over = true;
            else if (inter < __fmul_rn(t45, 0.9999995f)) over = false;
            else    over = (__fdiv_rn(inter, denom) > IOU_T);   // exact fallback
            bits = __ballot_sync(0xffffffffu, over && (j > i));
        }
        if (lane == 0) g_mask[b][T] = bits;
    }

    // ---- last-block election ----
    __threadfence();                            // publish mask words
    __syncthreads();
    if (tid == 0) {
        int prev = atomicAdd(&g_done[b], 1);
        isLast = (prev == MASK_BLKS_PER_B - 1);
    }
    __syncthreads();
    if (!isLast) return;
    __threadfence();                            // acquire others' mask writes

    // ---- greedy phase (smem union reused as mask cache) ----
    {
        const uint4* src = (const uint4*)g_mask[b];   // L2-hot, just written
        uint4* dst = (uint4*)U.Sm;
        #pragma unroll
        for (int u = 0; u < 8; u++) dst[tid + 256 * u] = src[tid + 256 * u];
    }
    if (tid < 16) Skw[tid] = g_kw[b][tid];
    __syncthreads();

    // Warp 0: greedy scan. Lane l (mirrored at l+16) owns removed-word l&15.
    if (tid < 32) {
        const int l16 = lane & 15;
        unsigned rem = Skw[l16];
        const unsigned* rowp = U.Sm + l16;      // this lane's mask column
        #pragma unroll 1
        for (int wb = 0; wb < 16; wb++) {
            unsigned cur = __shfl_sync(0xffffffffu, rem, wb);  // word wb tracker
            const unsigned* curp = U.Sm + wb;
            const int ib = wb << 5;
            unsigned prA = rowp[(ib + 0) << 4];
            unsigned pcA = curp[(ib + 0) << 4];
            unsigned prB = rowp[(ib + 1) << 4];
            unsigned pcB = curp[(ib + 1) << 4];
            #pragma unroll
            for (int bit = 0; bit < 32; bit++) {
                unsigned row = prA, cw = pcA;
                prA = prB; pcA = pcB;
                int nx = bit + 2; if (nx > 31) nx = 31;
                prB = rowp[(ib + nx) << 4];
                pcB = curp[(ib + nx) << 4];
                if (!((cur >> bit) & 1u)) {     // box ib+bit survives -> suppress
                    rem |= row;
                    cur |= cw;
                }
            }
        }
        if (lane < 16) Skw[lane] = rem;
    }
    __syncthreads();

    // ---- output [b, KDET, 9]: 2 slots per thread, loads gated by kept ----
    #pragma unroll
    for (int h = 0; h < 2; h++) {
        int sidx = tid + 256 * h;
        bool kept = !((Skw[sidx >> 5] >> (sidx & 31)) & 1u);
        float* orow = out + ((size_t)b * KDET + sidx) * 9;
        if (kept) {
            float4 bx = g_boxes[b][sidx];
            const float* r = pred + ((size_t)b * NPRED + g_six[b][sidx]) * 9;
            orow[0] = bx.x; orow[1] = bx.y; orow[2] = bx.z; orow[3] = bx.w;
            orow[4] = g_ssc[b][sidx];
            orow[5] = 0.0f;
            orow[6] = r[6]; orow[7] = r[7]; orow[8] = r[8];
        } else {
            #pragma unroll
            for (int q = 0; q < 9; q++) orow[q] = 0.0f;
        }
    }

    // reset for next graph replay (only this block is alive for batch b)
    __syncthreads();
    if (tid == 0) g_done[b] = 0;
}

// ---------------------------------------------------------------------------
extern "C" void kernel_launch(void* const* d_in, const int* in_sizes, int n_in,
                              void* d_out, int out_size) {
    const float* pred = (const float*)d_in[0];
    float* out = (float*)d_out;

    score_compact_kernel<<<dim3(K1_BLKS, NB), K1_THREADS>>>(pred);
    select_sort_kernel<<<NB, 1024>>>(pred);
    mask_greedy_kernel<<<dim3(MASK_BLKS_PER_B, NB), 256>>>(pred, out);
}

// round 7
// speedup vs baseline: 1.2276x; 1.0201x over previous
#include <cuda_runtime.h>
#include <cstdint>
#include <cstddef>

#define NB      64
#define NPRED   100800
#define KDET    512
#define CAP     8192
#define SEL     1024
#define CONF_T  0.7f
#define IOU_T   0.45f

#define KA_THREADS 1024
#define KA_RPT     8                        // rows per thread
#define KA_ROWS    (KA_THREADS * KA_RPT)    // 8192
#define KA_BLKS    13                       // 13*8192 = 106496 >= 100800
#define STG_CAP    1024                     // staging capacity (mean ~412/blk)

// Global scratch (__device__ arrays; no allocation).
__device__ float    g_sc[NB][CAP];
__device__ int      g_ix[NB][CAP];
__device__ int      g_cnt[NB];            // zero at load; reset by selector tail
__device__ int      g_done[NB];           // zero at load; reset by selector tail
__device__ float4   g_boxes[NB][KDET];
__device__ float    g_area[NB][KDET];
__device__ float    g_ssc[NB][KDET];
__device__ int      g_six[NB][KDET];
__device__ unsigned g_kw[NB][16];
__device__ unsigned g_mask[NB][KDET * 16];  // 2 MB

// ---------------------------------------------------------------------------
// Kernel A: streaming score+compact (whole chip, DRAM-bound) fused with a
// per-batch last-block select + bitonic-sort + gather tail that overlaps
// with other batches' streaming.
// ---------------------------------------------------------------------------
struct SmemA {
    union {
        struct { float sc[STG_CAP]; int ix[STG_CAP]; } stg;            // 8 KB
        struct { float bufS[2][SEL]; int bufI[2][SEL]; int hist[1024]; } sel; // 20 KB
    } u;
    int sCnt, blockBase, selCnt, b1s, isLast;
};

__global__ __launch_bounds__(KA_THREADS)
void score_select_kernel(const float* __restrict__ pred) {
    __shared__ SmemA S;
    const int b   = blockIdx.y;
    const int tid = threadIdx.x;
    const int r0  = blockIdx.x * KA_ROWS;
    if (tid == 0) S.sCnt = 0;
    __syncthreads();

    // ======================= Phase A: score + compact =======================
    const float* __restrict__ base = pred + (size_t)b * NPRED * 9;
    float a[KA_RPT], c[KA_RPT];
    int   rr[KA_RPT];
    #pragma unroll
    for (int k = 0; k < KA_RPT; k++) {          // front-batched loads (MLP 16)
        int r = r0 + k * KA_THREADS + tid;      // coalesced within each k
        rr[k] = r;
        bool ok = r < NPRED;
        const float* p = base + (size_t)r * 9;
        a[k] = ok ? __ldg(p + 4) : 0.0f;
        c[k] = ok ? __ldg(p + 5) : 0.0f;
    }
    #pragma unroll
    for (int k = 0; k < KA_RPT; k++) {
        float conf = __fmul_rn(a[k], c[k]);     // exact, matches reference
        if (conf > CONF_T) {
            int p = atomicAdd(&S.sCnt, 1);      // ~412 per block
            if (p < STG_CAP) { S.u.stg.sc[p] = conf; S.u.stg.ix[p] = rr[k]; }
        }
    }
    __syncthreads();
    if (tid == 0) S.blockBase = atomicAdd(&g_cnt[b], S.sCnt);  // ONE global atomic
    __syncthreads();

    {
        int n = min(S.sCnt, STG_CAP);
        int gbase = S.blockBase;
        for (int t = tid; t < n; t += KA_THREADS) {
            int p = gbase + t;
            if (p < CAP) { g_sc[b][p] = S.u.stg.sc[t]; g_ix[b][p] = S.u.stg.ix[t]; }
        }
    }

    // ==================== last-block election for batch b ====================
    __threadfence();                            // publish g_sc/g_ix/g_cnt
    __syncthreads();
    if (tid == 0) {
        int prev = atomicAdd(&g_done[b], 1);
        S.isLast = (prev == KA_BLKS - 1);
    }
    __syncthreads();
    if (!S.isLast) return;
    __threadfence();                            // acquire other blocks' writes

    // =================== Phase B: select + sort + gather ====================
    int cnt = g_cnt[b];
    if (cnt > CAP) cnt = CAP;

    // B1: histogram on score bits [22:13] (exponent fixed for (0.7,1))
    S.u.sel.hist[tid] = 0;
    if (tid == 0) { S.selCnt = 0; S.b1s = -1; }
    __syncthreads();
    for (int e = tid; e < cnt; e += 1024) {
        unsigned u = __float_as_uint(g_sc[b][e]);
        atomicAdd(&S.u.sel.hist[(u >> 13) & 1023], 1);
    }
    __syncthreads();

    // B2: suffix sum + boundary bin
    for (int d = 1; d < 1024; d <<= 1) {
        int v = (tid + d < 1024) ? S.u.sel.hist[tid + d] : 0;
        __syncthreads();
        S.u.sel.hist[tid] += v;
        __syncthreads();
    }
    int target = (cnt < KDET) ? cnt : KDET;
    if (S.u.sel.hist[tid] >= target) atomicMax(&S.b1s, tid);
    __syncthreads();
    int b1 = S.b1s;

    // B3: collect bins >= b1 (~ target + boundary spill)
    for (int e = tid; e < cnt; e += 1024) {
        float sc = g_sc[b][e];
        if ((int)((__float_as_uint(sc) >> 13) & 1023) >= b1) {
            int p = atomicAdd(&S.selCnt, 1);
            if (p < SEL) { S.u.sel.bufS[0][p] = sc; S.u.sel.bufI[0][p] = g_ix[b][e]; }
        }
    }
    __syncthreads();
    int selN = S.selCnt; if (selN > SEL) selN = SEL;
    if (tid >= selN) { S.u.sel.bufS[0][tid] = -1.0f; S.u.sel.bufI[0][tid] = 0x7fffffff; }
    __syncthreads();

    // B4: hybrid bitonic sort (score desc, idx asc == lax.top_k order)
    float s  = S.u.sel.bufS[0][tid];
    int   ix = S.u.sel.bufI[0][tid];
    int   pb = 1;
    for (int k = 2; k <= SEL; k <<= 1) {
        for (int j = k >> 1; j > 0; j >>= 1) {
            float s2; int i2;
            if (j >= 32) {
                S.u.sel.bufS[pb][tid] = s; S.u.sel.bufI[pb][tid] = ix;
                __syncthreads();
                s2 = S.u.sel.bufS[pb][tid ^ j]; i2 = S.u.sel.bufI[pb][tid ^ j];
                pb ^= 1;
            } else {
                s2 = __shfl_xor_sync(0xffffffffu, s, j);
                i2 = __shfl_xor_sync(0xffffffffu, ix, j);
            }
            bool want_first = ((tid & k) == 0);
            bool i_low      = ((tid & j) == 0);
            bool mine_better = (s > s2) || (s == s2 && ix < i2);
            if (mine_better != (i_low == want_first)) { s = s2; ix = i2; }
        }
    }

    // B5: gather top-512 rows -> boxes/areas/validity, store to global.
    if (tid < KDET) {
        float4 bx = make_float4(0.f, 0.f, 0.f, 0.f);
        float  ar = 0.f;
        bool valid = s > CONF_T;
        if (valid) {
            const float* r = pred + ((size_t)b * NPRED + ix) * 9;
            float cx = r[0], cy = r[1];
            float hw = __fmul_rn(r[2], 0.5f);     // exact; matches ref rounding
            float hh = __fmul_rn(r[3], 0.5f);
            bx.x = __fsub_rn(cx, hw); bx.y = __fsub_rn(cy, hh);
            bx.z = __fadd_rn(cx, hw); bx.w = __fadd_rn(cy, hh);
            ar = __fmul_rn(__fsub_rn(bx.z, bx.x), __fsub_rn(bx.w, bx.y));
        }
        g_boxes[b][tid] = bx;
        g_area[b][tid]  = ar;
        g_ssc[b][tid]   = s;
        g_six[b][tid]   = ix;
        unsigned bal = __ballot_sync(0xffffffffu, valid);
        if ((tid & 31) == 0) g_kw[b][tid >> 5] = ~bal;  // removed-init = !valid
    }
    // reset counters for next graph replay (only this block alive for batch b)
    __syncthreads();
    if (tid == 0) { g_cnt[b] = 0; g_done[b] = 0; }
}

// ---------------------------------------------------------------------------
// Kernel 2b: full-chip IoU suppression bitmask (round-4 version, verbatim).
// ---------------------------------------------------------------------------
__global__ __launch_bounds__(256)
void mask_kernel() {
    __shared__ float4 Sb[KDET];    // 8 KB
    __shared__ float  Sa[KDET];    // 2 KB
    const int tid  = threadIdx.x;
    const int lane = tid & 31;
    const int wid  = tid >> 5;
    const int b    = blockIdx.y;

    for (int q = tid; q < KDET; q += 256) { Sb[q] = g_boxes[b][q]; Sa[q] = g_area[b][q]; }
    __syncthreads();

    int wg = blockIdx.x * 8 + wid;             // 0..127 within batch
    for (int T = wg; T < KDET * 16; T += 128) {
        int i = T >> 4;
        int w = T & 15;
        unsigned bits = 0;
        if ((w << 5) + 31 > i) {               // word contains some j > i
            float4 bi = Sb[i];                 // LDS broadcast
            float  ai = Sa[i];
            int    j  = (w << 5) + lane;
            float4 bj = Sb[j];
            float  aj = Sa[j];
            float xx1 = fmaxf(bi.x, bj.x), yy1 = fmaxf(bi.y, bj.y);
            float xx2 = fminf(bi.z, bj.z), yy2 = fminf(bi.w, bj.w);
            float iw = fmaxf(__fsub_rn(xx2, xx1), 0.f);
            float ih = fmaxf(__fsub_rn(yy2, yy1), 0.f);
            float inter = __fmul_rn(iw, ih);
            float denom = __fadd_rn(__fsub_rn(__fadd_rn(ai, aj), inter), 1e-7f);
            float t45 = __fmul_rn(denom, IOU_T);
            bool over;
            if      (inter > __fmul_rn(t45, 1.0000005f)) over = true;
            else if (inter < __fmul_rn(t45, 0.9999995f)) over = false;
            else    over = (__fdiv_rn(inter, denom) > IOU_T);   // exact fallback
            bits = __ballot_sync(0xffffffffu, over && (j > i));
        }
        if (lane == 0) g_mask[b][T] = bits;
    }
}

// ---------------------------------------------------------------------------
// Kernel 2c: warp-cooperative greedy suppression + output (round-4 version).
// ---------------------------------------------------------------------------
__global__ __launch_bounds__(512)
void greedy_out_kernel(const float* __restrict__ pred, float* __restrict__ out) {
    __shared__ unsigned Sm[KDET * 16];   // 32 KB
    __shared__ unsigned Skw[16];
    const int tid  = threadIdx.x;
    const int lane = tid & 31;
    const int b    = blockIdx.x;

    {   // stage mask into smem, coalesced uint4
        const uint4* src = (const uint4*)g_mask[b];
        uint4* dst = (uint4*)Sm;
        #pragma unroll
        for (int u = 0; u < 4; u++) dst[tid + 512 * u] = src[tid + 512 * u];
    }
    if (tid < 16) Skw[tid] = g_kw[b][tid];
    __syncthreads();

    // Warp 0: greedy scan. Lane l (mirrored at l+16) owns removed-word l&15.
    if (tid < 32) {
        const int l16 = lane & 15;
        unsigned rem = Skw[l16];
        const unsigned* rowp = Sm + l16;       // this lane's mask column
        #pragma unroll 1
        for (int wb = 0; wb < 16; wb++) {
            unsigned cur = __shfl_sync(0xffffffffu, rem, wb);  // word wb tracker
            const unsigned* curp = Sm + wb;
            const int ib = wb << 5;
            unsigned prA = rowp[(ib + 0) << 4];
            unsigned pcA = curp[(ib + 0) << 4];
            unsigned prB = rowp[(ib + 1) << 4];
            unsigned pcB = curp[(ib + 1) << 4];
            #pragma unroll
            for (int bit = 0; bit < 32; bit++) {
                unsigned row = prA, cw = pcA;
                prA = prB; pcA = pcB;
                int nx = bit + 2; if (nx > 31) nx = 31;
                prB = rowp[(ib + nx) << 4];
                pcB = curp[(ib + nx) << 4];
                if (!((cur >> bit) & 1u)) {    // box ib+bit survives -> suppress
                    rem |= row;
                    cur |= cw;
                }
            }
        }
        if (lane < 16) Skw[lane] = rem;
    }
    __syncthreads();

    // Output [b, KDET, 9]; loads gated by kept (issued post-barrier)
    bool kept = !((Skw[tid >> 5] >> (tid & 31)) & 1u);
    float* orow = out + ((size_t)b * KDET + tid) * 9;
    if (kept) {
        float4 bx = g_boxes[b][tid];
        const float* r = pred + ((size_t)b * NPRED + g_six[b][tid]) * 9;
        orow[0] = bx.x; orow[1] = bx.y; orow[2] = bx.z; orow[3] = bx.w;
        orow[4] = g_ssc[b][tid];
        orow[5] = 0.0f;
        orow[6] = r[6]; orow[7] = r[7]; orow[8] = r[8];
    } else {
        #pragma unroll
        for (int q = 0; q < 9; q++) orow[q] = 0.0f;
    }
}

// ---------------------------------------------------------------------------
extern "C" void kernel_launch(void* const* d_in, const int* in_sizes, int n_in,
                              void* d_out, int out_size) {
    const float* pred = (const float*)d_in[0];
    float* out = (float*)d_out;

    score_select_kernel<<<dim3(KA_BLKS, NB), KA_THREADS>>>(pred);
    mask_kernel<<<dim3(16, NB), 256>>>();
    greedy_out_kernel<<<NB, KDET>>>(pred, out);
}

// round 10
// speedup vs baseline: 1.4210x; 1.1576x over previous
#include <cuda_runtime.h>
#include <cstdint>
#include <cstddef>

#define NB      64
#define NPRED   100800
#define KDET    512
#define CAP     8192
#define SEL     1024
#define CONF_T  0.7f
#define IOU_T   0.45f

#define K1_THREADS 256
#define K1_RPT     8                       // rows per thread
#define K1_ROWS    (K1_THREADS * K1_RPT)   // 2048
#define K1_BLKS    50                      // 50*2048 >= 100800

// Global scratch (__device__ arrays; no allocation).
__device__ float    g_sc[NB][CAP];
__device__ int      g_ix[NB][CAP];
__device__ int      g_cnt[NB];            // zero at load; reset by select_sort
__device__ float4   g_boxes[NB][KDET];
__device__ float    g_area[NB][KDET];
__device__ float    g_ssc[NB][KDET];
__device__ int      g_six[NB][KDET];
__device__ unsigned g_kw[NB][16];
// Zero-initialized; sub-diagonal words are NEVER written and stay 0 forever.
__device__ unsigned g_mask[NB][KDET * 16];  // 2 MB

// ---------------------------------------------------------------------------
// Kernel 1: direct-LDG scoring + two-level compaction (round-4 verbatim).
// ---------------------------------------------------------------------------
__global__ __launch_bounds__(K1_THREADS)
void score_compact_kernel(const float* __restrict__ pred) {
    __shared__ float stg_sc[256];
    __shared__ int   stg_ix[256];
    __shared__ int   sCnt, blockBase;

    const int b   = blockIdx.y;
    const int tid = threadIdx.x;
    const int r0  = blockIdx.x * K1_ROWS;
    if (tid == 0) sCnt = 0;
    __syncthreads();

    const float* __restrict__ base = pred + (size_t)b * NPRED * 9;

    float a[K1_RPT], c[K1_RPT];
    int   rr[K1_RPT];
    #pragma unroll
    for (int k = 0; k < K1_RPT; k++) {          // front-batched loads (MLP 16)
        int r = r0 + k * K1_THREADS + tid;      // coalesced within each k
        rr[k] = r;
        bool ok = r < NPRED;
        const float* p = base + (size_t)r * 9;
        a[k] = ok ? __ldg(p + 4) : 0.0f;
        c[k] = ok ? __ldg(p + 5) : 0.0f;
    }
    #pragma unroll
    for (int k = 0; k < K1_RPT; k++) {
        float conf = __fmul_rn(a[k], c[k]);     // exact, matches reference
        if (conf > CONF_T) {
            int p = atomicAdd(&sCnt, 1);        // ~100 per block
            if (p < 256) { stg_sc[p] = conf; stg_ix[p] = rr[k]; }
        }
    }
    __syncthreads();
    if (tid == 0) blockBase = atomicAdd(&g_cnt[b], sCnt);   // ONE global atomic
    __syncthreads();

    int n = min(sCnt, 256);
    int gbase = blockBase;
    for (int t = tid; t < n; t += K1_THREADS) {
        int p = gbase + t;
        if (p < CAP) { g_sc[b][p] = stg_sc[t]; g_ix[b][p] = stg_ix[t]; }
    }
}

// ---------------------------------------------------------------------------
// Kernel 2a: radix-select (warp-shfl suffix scan) + hybrid bitonic(1024).
// ---------------------------------------------------------------------------
__global__ __launch_bounds__(1024, 1)
void select_sort_kernel(const float* __restrict__ pred) {
    __shared__ float bufS[2][SEL];     // 8 KB (double-buffer)
    __shared__ int   bufI[2][SEL];     // 8 KB
    __shared__ int   hist[1024];       // 4 KB
    __shared__ int   warpOff[32];
    __shared__ int   selCnt, b1s;

    const int tid  = threadIdx.x;
    const int lane = tid & 31;
    const int wrp  = tid >> 5;
    const int b    = blockIdx.x;
    int cnt = g_cnt[b];
    if (cnt > CAP) cnt = CAP;

    // Phase 1: histogram on score bits [22:13] (exponent fixed for (0.7,1))
    hist[tid] = 0;
    if (tid == 0) { selCnt = 0; b1s = -1; }
    __syncthreads();
    for (int e = tid; e < cnt; e += 1024) {
        unsigned u = __float_as_uint(g_sc[b][e]);
        atomicAdd(&hist[(u >> 13) & 1023], 1);
    }
    __syncthreads();

    // Phase 2: hierarchical inclusive SUFFIX scan (3 barriers vs 20)
    int val = hist[tid];
    #pragma unroll
    for (int d = 1; d < 32; d <<= 1) {
        int v = __shfl_down_sync(0xffffffffu, val, d);
        if (lane + d < 32) val += v;
    }
    if (lane == 0) warpOff[wrp] = val;          // warp total
    __syncthreads();
    if (wrp == 0) {
        int t = warpOff[lane];
        int tot = t;
        #pragma unroll
        for (int d = 1; d < 32; d <<= 1) {
            int v = __shfl_down_sync(0xffffffffu, tot, d);
            if (lane + d < 32) tot += v;
        }
        warpOff[lane] = tot - t;                // exclusive suffix of warp totals
    }
    __syncthreads();
    int suffix = val + warpOff[wrp];            // sum of hist[u] for u >= tid
    int target = (cnt < KDET) ? cnt : KDET;
    if (suffix >= target) atomicMax(&b1s, tid);
    __syncthreads();
    int b1 = b1s;

    // Phase 3: collect bins >= b1 (~ target + boundary spill)
    for (int e = tid; e < cnt; e += 1024) {
        float sc = g_sc[b][e];
        if ((int)((__float_as_uint(sc) >> 13) & 1023) >= b1) {
            int p = atomicAdd(&selCnt, 1);
            if (p < SEL) { bufS[0][p] = sc; bufI[0][p] = g_ix[b][e]; }
        }
    }
    __syncthreads();
    int selN = selCnt; if (selN > SEL) selN = SEL;
    if (tid >= selN) { bufS[0][tid] = -1.0f; bufI[0][tid] = 0x7fffffff; }
    __syncthreads();

    // Phase 4: hybrid bitonic sort (score desc, idx asc == lax.top_k order)
    float s  = bufS[0][tid];
    int   ix = bufI[0][tid];
    int   pb = 1;
    for (int k = 2; k <= SEL; k <<= 1) {
        for (int j = k >> 1; j > 0; j >>= 1) {
            float s2; int i2;
            if (j >= 32) {
                bufS[pb][tid] = s; bufI[pb][tid] = ix;
                __syncthreads();
                s2 = bufS[pb][tid ^ j]; i2 = bufI[pb][tid ^ j];
                pb ^= 1;
            } else {
                s2 = __shfl_xor_sync(0xffffffffu, s, j);
                i2 = __shfl_xor_sync(0xffffffffu, ix, j);
            }
            bool want_first = ((tid & k) == 0);
            bool i_low      = ((tid & j) == 0);
            bool mine_better = (s > s2) || (s == s2 && ix < i2);
            if (mine_better != (i_low == want_first)) { s = s2; ix = i2; }
        }
    }

    // Phase 5: gather top-512 rows -> boxes/areas/validity, store to global.
    if (tid < KDET) {
        float4 bx = make_float4(0.f, 0.f, 0.f, 0.f);
        float  ar = 0.f;
        bool valid = s > CONF_T;
        if (valid) {
            const float* r = pred + ((size_t)b * NPRED + ix) * 9;
            float cx = r[0], cy = r[1];
            float hw = __fmul_rn(r[2], 0.5f);     // exact; matches ref rounding
            float hh = __fmul_rn(r[3], 0.5f);
            bx.x = __fsub_rn(cx, hw); bx.y = __fsub_rn(cy, hh);
            bx.z = __fadd_rn(cx, hw); bx.w = __fadd_rn(cy, hh);
            ar = __fmul_rn(__fsub_rn(bx.z, bx.x), __fsub_rn(bx.w, bx.y));
        }
        g_boxes[b][tid] = bx;
        g_area[b][tid]  = ar;
        g_ssc[b][tid]   = s;
        g_six[b][tid]   = ix;
        unsigned bal = __ballot_sync(0xffffffffu, valid);
        if (lane == 0) g_kw[b][tid >> 5] = ~bal;  // removed-init = !valid
    }
    if (tid == 0) g_cnt[b] = 0;   // reset for next graph replay
}

// ---------------------------------------------------------------------------
// Kernel 2b: IoU mask, upper-triangle words only (4352 vs 8192 word-tasks).
// Warp owns full rows i = wg + 128*k; inner loop w = i>>5 .. 15.
// Sub-diagonal words of g_mask are never written: zero-init keeps them 0.
// ---------------------------------------------------------------------------
__global__ __launch_bounds__(256)
void mask_kernel() {
    __shared__ float4 Sb[KDET];    // 8 KB
    __shared__ float  Sa[KDET];    // 2 KB
    const int tid  = threadIdx.x;
    const int lane = tid & 31;
    const int wid  = tid >> 5;
    const int b    = blockIdx.y;

    for (int q = tid; q < KDET; q += 256) { Sb[q] = g_boxes[b][q]; Sa[q] = g_area[b][q]; }
    __syncthreads();

    const int wg = blockIdx.x * 8 + wid;       // 0..127 within batch
    #pragma unroll 1
    for (int i = wg; i < KDET; i += 128) {
        float4 bi = Sb[i];                     // LDS broadcast, once per row
        float  ai = Sa[i];
        unsigned* mrow = &g_mask[b][i << 4];
        #pragma unroll 1
        for (int w = (i >> 5); w < 16; w++) {
            int    j  = (w << 5) + lane;
            float4 bj = Sb[j];
            float  aj = Sa[j];
            float xx1 = fmaxf(bi.x, bj.x), yy1 = fmaxf(bi.y, bj.y);
            float xx2 = fminf(bi.z, bj.z), yy2 = fminf(bi.w, bj.w);
            float iw = fmaxf(__fsub_rn(xx2, xx1), 0.f);
            float ih = fmaxf(__fsub_rn(yy2, yy1), 0.f);
            float inter = __fmul_rn(iw, ih);
            float denom = __fadd_rn(__fsub_rn(__fadd_rn(ai, aj), inter), 1e-7f);
            float t45 = __fmul_rn(denom, IOU_T);
            bool over;
            if      (inter > __fmul_rn(t45, 1.0000005f)) over = true;
            else if (inter < __fmul_rn(t45, 0.9999995f)) over = false;
            else    over = (__fdiv_rn(inter, denom) > IOU_T);   // exact fallback
            unsigned bits = __ballot_sync(0xffffffffu, over && (j > i));
            if (lane == 0) mrow[w] = bits;
        }
    }
}

// ---------------------------------------------------------------------------
// Kernel 2c: warp-cooperative greedy suppression + output (round-4 verbatim).
// ---------------------------------------------------------------------------
__global__ __launch_bounds__(512)
void greedy_out_kernel(const float* __restrict__ pred, float* __restrict__ out) {
    __shared__ unsigned Sm[KDET * 16];   // 32 KB
    __shared__ unsigned Skw[16];
    const int tid  = threadIdx.x;
    const int lane = tid & 31;
    const int b    = blockIdx.x;

    {   // stage mask into smem, coalesced uint4
        const uint4* src = (const uint4*)g_mask[b];
        uint4* dst = (uint4*)Sm;
        #pragma unroll
        for (int u = 0; u < 4; u++) dst[tid + 512 * u] = src[tid + 512 * u];
    }
    if (tid < 16) Skw[tid] = g_kw[b][tid];
    __syncthreads();

    // Warp 0: greedy scan. Lane l (mirrored at l+16) owns removed-word l&15.
    if (tid < 32) {
        const int l16 = lane & 15;
        unsigned rem = Skw[l16];
        const unsigned* rowp = Sm + l16;       // this lane's mask column
        #pragma unroll 1
        for (int wb = 0; wb < 16; wb++) {
            unsigned cur = __shfl_sync(0xffffffffu, rem, wb);  // word wb tracker
            const unsigned* curp = Sm + wb;
            const int ib = wb << 5;
            unsigned prA = rowp[(ib + 0) << 4];
            unsigned pcA = curp[(ib + 0) << 4];
            unsigned prB = rowp[(ib + 1) << 4];
            unsigned pcB = curp[(ib + 1) << 4];
            #pragma unroll
            for (int bit = 0; bit < 32; bit++) {
                unsigned row = prA, cw = pcA;
                prA = prB; pcA = pcB;
                int nx = bit + 2; if (nx > 31) nx = 31;
                prB = rowp[(ib + nx) << 4];
                pcB = curp[(ib + nx) << 4];
                if (!((cur >> bit) & 1u)) {    // box ib+bit survives -> suppress
                    rem |= row;
                    cur |= cw;
                }
            }
        }
        if (lane < 16) Skw[lane] = rem;
    }
    __syncthreads();

    // Output [b, KDET, 9]; loads gated by kept (issued post-barrier)
    bool kept = !((Skw[tid >> 5] >> (tid & 31)) & 1u);
    float* orow = out + ((size_t)b * KDET + tid) * 9;
    if (kept) {
        float4 bx = g_boxes[b][tid];
        const float* r = pred + ((size_t)b * NPRED + g_six[b][tid]) * 9;
        orow[0] = bx.x; orow[1] = bx.y; orow[2] = bx.z; orow[3] = bx.w;
        orow[4] = g_ssc[b][tid];
        orow[5] = 0.0f;
        orow[6] = r[6]; orow[7] = r[7]; orow[8] = r[8];
    } else {
        #pragma unroll
        for (int q = 0; q < 9; q++) orow[q] = 0.0f;
    }
}

// ---------------------------------------------------------------------------
extern "C" void kernel_launch(void* const* d_in, const int* in_sizes, int n_in,
                              void* d_out, int out_size) {
    const float* pred = (const float*)d_in[0];
    float* out = (float*)d_out;

    score_compact_kernel<<<dim3(K1_BLKS, NB), K1_THREADS>>>(pred);
    select_sort_kernel<<<NB, 1024>>>(pred);
    mask_kernel<<<dim3(16, NB), 256>>>();
    greedy_out_kernel<<<NB, KDET>>>(pred, out);
}